// round 10
// baseline (speedup 1.0000x reference)
#include <cuda_runtime.h>
#include <cstdint>

// FHE BSGS rotate/mul/accumulate. Fixed shapes: x[64,65536] f32, diag[16,65536] f32,
// stride=1, reps=1 -> out[b,s] = sum_t x[b,(s2+2^t)&65535] * diag[t,s2], s2 = s^32768.
// Tap-split design: each output quad is owned by a 4-lane team (sub = lane>>3),
// sub handles taps 4*sub..4*sub+3; partials merged with shfl_xor(8|16).
#define SLOTS 65536
#define SQ    (SLOTS / 4)     // 16384 quads per row
#define QM    (SQ - 1)
#define BATCH 64
#define BPC   8               // batches per CTA
#define TPB   256
#define TILE  64              // output quads per CTA (8 warps x 8 quads)

typedef unsigned long long u64;

__device__ __forceinline__ u64 fma2(u64 x, u64 d, u64 a) {
    u64 r; asm("fma.rn.f32x2 %0, %1, %2, %3;" : "=l"(r) : "l"(x), "l"(d), "l"(a)); return r;
}
__device__ __forceinline__ u64 mul2(u64 x, u64 d) {
    u64 r; asm("mul.rn.f32x2 %0, %1, %2;" : "=l"(r) : "l"(x), "l"(d)); return r;
}
__device__ __forceinline__ u64 add2(u64 x, u64 y) {
    u64 r; asm("add.rn.f32x2 %0, %1, %2;" : "=l"(r) : "l"(x), "l"(y)); return r;
}
__device__ __forceinline__ u64 pack2(float lo, float hi) {
    u64 r; asm("mov.b64 %0, {%1, %2};" : "=l"(r) : "f"(lo), "f"(hi)); return r;
}

__global__ __launch_bounds__(TPB, 3)
void fhe_bsgs_ts(const float* __restrict__ x,
                 const float* __restrict__ diag,
                 float* __restrict__ out)
{
    const int tid  = threadIdx.x;
    const int lane = tid & 31;
    const int sub  = lane >> 3;                    // tap group 0..3
    const int oq   = (tid >> 5) * 8 + (lane & 7);  // output quad within tile: 0..63
    const int Sq   = blockIdx.x * TILE + oq;       // global output quad
    const int q2   = Sq ^ 8192;                    // rolled (s2-space) quad
    const int b0   = blockIdx.y * BPC;

    const float4*     x4 = reinterpret_cast<const float4*>(x);
    const ulonglong2* x8 = reinterpret_cast<const ulonglong2*>(x);
    const float4*     d4 = reinterpret_cast<const float4*>(diag);
    const ulonglong2* d8 = reinterpret_cast<const ulonglong2*>(diag);
    ulonglong2*       o8 = reinterpret_cast<ulonglong2*>(out);

    if (sub == 0) {
        // ---- taps t=0..3 (shifts 1,2,4,8 slots). Loads: A=q2, B=q2+1, C=q2+2 ----
        const float4 dvs0 = d4[0 * SQ + q2];
        const float4 dvs1 = d4[1 * SQ + q2];
        const float4 dvs2 = d4[2 * SQ + q2];
        const ulonglong2 dvp3 = d8[3 * SQ + q2];

        const unsigned qA = (unsigned)q2;
        const unsigned qB = (unsigned)(q2 + 1) & QM;
        const unsigned qC = (unsigned)(q2 + 2) & QM;

        #pragma unroll 2
        for (int i = 0; i < BPC; i++) {
            const int b = b0 + i;
            const float4 A  = x4[(size_t)b * SQ + qA];
            const float4 Bv = x4[(size_t)b * SQ + qB];
            const ulonglong2 C = x8[(size_t)b * SQ + qC];

            float s0, s1, s2, s3;
            s0 = A.y  * dvs0.x;               // t=0: (A.y,A.z,A.w,B.x)
            s1 = A.z  * dvs0.y;
            s2 = A.w  * dvs0.z;
            s3 = Bv.x * dvs0.w;
            s0 = fmaf(A.z,  dvs1.x, s0);      // t=1: (A.z,A.w,B.x,B.y)
            s1 = fmaf(A.w,  dvs1.y, s1);
            s2 = fmaf(Bv.x, dvs1.z, s2);
            s3 = fmaf(Bv.y, dvs1.w, s3);
            s0 = fmaf(Bv.x, dvs2.x, s0);      // t=2: B
            s1 = fmaf(Bv.y, dvs2.y, s1);
            s2 = fmaf(Bv.z, dvs2.z, s2);
            s3 = fmaf(Bv.w, dvs2.w, s3);

            u64 alo = pack2(s0, s1);
            u64 ahi = pack2(s2, s3);
            alo = fma2(C.x, dvp3.x, alo);     // t=3
            ahi = fma2(C.y, dvp3.y, ahi);

            // butterfly reduce across sub groups (lanes reconverged here)
            alo = add2(alo, __shfl_xor_sync(0xffffffffu, alo, 8));
            ahi = add2(ahi, __shfl_xor_sync(0xffffffffu, ahi, 8));
            alo = add2(alo, __shfl_xor_sync(0xffffffffu, alo, 16));
            ahi = add2(ahi, __shfl_xor_sync(0xffffffffu, ahi, 16));

            o8[(size_t)b * SQ + Sq] = make_ulonglong2(alo, ahi);
        }
    } else {
        // ---- taps t=4*sub .. 4*sub+3 (all quad-aligned: offset 1<<(t-2) quads) ----
        const int tb = 4 * sub;
        ulonglong2 dv[4];
        unsigned qo[4];
        #pragma unroll
        for (int j = 0; j < 4; j++) {
            dv[j] = d8[(tb + j) * SQ + q2];
            qo[j] = (unsigned)(q2 + (1 << (tb + j - 2))) & QM;
        }

        #pragma unroll 2
        for (int i = 0; i < BPC; i++) {
            const int b = b0 + i;
            const ulonglong2* __restrict__ xr = x8 + (size_t)b * SQ;

            const ulonglong2 X0 = xr[qo[0]];
            const ulonglong2 X1 = xr[qo[1]];
            const ulonglong2 X2 = xr[qo[2]];
            const ulonglong2 X3 = xr[qo[3]];

            u64 alo = mul2(X0.x, dv[0].x);
            u64 ahi = mul2(X0.y, dv[0].y);
            alo = fma2(X1.x, dv[1].x, alo);  ahi = fma2(X1.y, dv[1].y, ahi);
            alo = fma2(X2.x, dv[2].x, alo);  ahi = fma2(X2.y, dv[2].y, ahi);
            alo = fma2(X3.x, dv[3].x, alo);  ahi = fma2(X3.y, dv[3].y, ahi);

            alo = add2(alo, __shfl_xor_sync(0xffffffffu, alo, 8));
            ahi = add2(ahi, __shfl_xor_sync(0xffffffffu, ahi, 8));
            alo = add2(alo, __shfl_xor_sync(0xffffffffu, alo, 16));
            ahi = add2(ahi, __shfl_xor_sync(0xffffffffu, ahi, 16));
            // only sub==0 lanes store; nothing to do here
            (void)alo; (void)ahi;
        }
    }
}

extern "C" void kernel_launch(void* const* d_in, const int* in_sizes, int n_in,
                              void* d_out, int out_size)
{
    const float* x    = (const float*)d_in[0];
    const float* diag = (const float*)d_in[1];
    float* out = (float*)d_out;

    dim3 grid(SQ / TILE, BATCH / BPC);   // (256 tiles, 8 batch-groups) = 2048 CTAs
    fhe_bsgs_ts<<<grid, TPB>>>(x, diag, out);
}

// round 11
// speedup vs baseline: 3.4288x; 3.4288x over previous
#include <cuda_runtime.h>
#include <cstdint>

// FHE BSGS rotate/mul/accumulate. Fixed shapes: x[64,65536] f32, diag[16,65536] f32,
// stride=1, reps=1 -> out[b,s] = sum_t x[b,(s2+2^t)&65535] * diag[t,s2], s2 = s^32768.
// Tap-outer / batch-inner register blocking: dv held 1 tap at a time (4 regs),
// 4 batch accumulators per thread, near taps from a one-shot smem stage.
#define SLOTS 65536
#define SQ    (SLOTS / 4)     // 16384 quads per row
#define QM    (SQ - 1)
#define BATCH 64
#define BPC   4               // batches per CTA (all staged at once)
#define TPB   256             // 1 output quad per thread -> 256-quad tile
#define NEARQ 768             // near union: 256 tile + 512 reach (shifts <= 2048 slots)

typedef unsigned long long u64;

__device__ __forceinline__ void cpasync16(uint32_t saddr, const float4* g) {
    asm volatile("cp.async.cg.shared.global [%0], [%1], 16;\n" :: "r"(saddr), "l"(g));
}
__device__ __forceinline__ void cp_commit() { asm volatile("cp.async.commit_group;\n"); }
__device__ __forceinline__ void cp_wait0()  { asm volatile("cp.async.wait_group 0;\n"); }

__device__ __forceinline__ u64 fma2(u64 x, u64 d, u64 a) {
    u64 r; asm("fma.rn.f32x2 %0, %1, %2, %3;" : "=l"(r) : "l"(x), "l"(d), "l"(a)); return r;
}
__device__ __forceinline__ u64 pack2(float lo, float hi) {
    u64 r; asm("mov.b64 %0, {%1, %2};" : "=l"(r) : "f"(lo), "f"(hi)); return r;
}

__global__ __launch_bounds__(TPB, 3)
void fhe_bsgs_tb(const float* __restrict__ x,
                 const float* __restrict__ diag,
                 float* __restrict__ out)
{
    __shared__ float4 sx[BPC][NEARQ];   // 49152 B

    const int tid = threadIdx.x;
    const int Sq  = blockIdx.x * TPB + tid;     // output quad
    const int Tq  = (blockIdx.x * TPB) ^ 8192;  // tile base in s2 space (256-aligned)
    const int q2  = Tq + tid;                   // rolled quad for this thread
    const int b0  = blockIdx.y * BPC;

    const float4*     x4 = reinterpret_cast<const float4*>(x);
    const ulonglong2* x8 = reinterpret_cast<const ulonglong2*>(x);
    const float4*     d4 = reinterpret_cast<const float4*>(diag);
    const ulonglong2* d8 = reinterpret_cast<const ulonglong2*>(diag);

    // One-shot stage: near unions for all BPC batches (12 cp.asyncs/thread).
    #pragma unroll
    for (int b = 0; b < BPC; b++) {
        const float4* __restrict__ xb = x4 + (size_t)(b0 + b) * SQ;
        const uint32_t sb = (uint32_t)__cvta_generic_to_shared(&sx[b][0]);
        #pragma unroll
        for (int r = 0; r < 3; r++) {
            const int k = tid + 256 * r;
            cpasync16(sb + k * 16, xb + ((Tq + k) & QM));
        }
    }
    cp_commit();
    cp_wait0();
    __syncthreads();     // the only barrier in the kernel

    u64 accLo[BPC], accHi[BPC];

    // ---- t=0..2 (misaligned windows) from smem: A = quad tid, B = quad tid+1 ----
    {
        const float4 dvs0 = d4[0 * SQ + q2];
        const float4 dvs1 = d4[1 * SQ + q2];
        const float4 dvs2 = d4[2 * SQ + q2];
        #pragma unroll
        for (int b = 0; b < BPC; b++) {
            const float4 A  = sx[b][tid];
            const float4 Bv = sx[b][tid + 1];
            float s0, s1, s2, s3;
            s0 = A.y  * dvs0.x;               // t=0: (A.y,A.z,A.w,B.x)
            s1 = A.z  * dvs0.y;
            s2 = A.w  * dvs0.z;
            s3 = Bv.x * dvs0.w;
            s0 = fmaf(A.z,  dvs1.x, s0);      // t=1: (A.z,A.w,B.x,B.y)
            s1 = fmaf(A.w,  dvs1.y, s1);
            s2 = fmaf(Bv.x, dvs1.z, s2);
            s3 = fmaf(Bv.y, dvs1.w, s3);
            s0 = fmaf(Bv.x, dvs2.x, s0);      // t=2: B
            s1 = fmaf(Bv.y, dvs2.y, s1);
            s2 = fmaf(Bv.z, dvs2.z, s2);
            s3 = fmaf(Bv.w, dvs2.w, s3);
            accLo[b] = pack2(s0, s1);
            accHi[b] = pack2(s2, s3);
        }
    }

    // ---- t=3..11 (offsets 2..512 quads) from smem; dv loaded per tap ----
    #pragma unroll 2
    for (int t = 3; t <= 11; t++) {
        const ulonglong2 dv = d8[t * SQ + q2];
        const int off = tid + (1 << (t - 2));
        #pragma unroll
        for (int b = 0; b < BPC; b++) {
            const ulonglong2 X = *reinterpret_cast<const ulonglong2*>(&sx[b][off]);
            accLo[b] = fma2(X.x, dv.x, accLo[b]);
            accHi[b] = fma2(X.y, dv.y, accHi[b]);
        }
    }

    // ---- t=12..15 (offsets 1024..8192 quads): direct coalesced LDG ----
    #pragma unroll 2
    for (int t = 12; t <= 15; t++) {
        const ulonglong2 dv = d8[t * SQ + q2];
        const unsigned qf = (unsigned)(q2 + (1 << (t - 2))) & QM;
        #pragma unroll
        for (int b = 0; b < BPC; b++) {
            const ulonglong2 X = x8[(size_t)(b0 + b) * SQ + qf];
            accLo[b] = fma2(X.x, dv.x, accLo[b]);
            accHi[b] = fma2(X.y, dv.y, accHi[b]);
        }
    }

    #pragma unroll
    for (int b = 0; b < BPC; b++)
        reinterpret_cast<ulonglong2*>(out)[(size_t)(b0 + b) * SQ + Sq] =
            make_ulonglong2(accLo[b], accHi[b]);
}

extern "C" void kernel_launch(void* const* d_in, const int* in_sizes, int n_in,
                              void* d_out, int out_size)
{
    const float* x    = (const float*)d_in[0];
    const float* diag = (const float*)d_in[1];
    float* out = (float*)d_out;

    dim3 grid(SQ / TPB, BATCH / BPC);   // (64 tiles, 16 batch-groups) = 1024 CTAs
    fhe_bsgs_tb<<<grid, TPB>>>(x, diag, out);
}